// round 1
// baseline (speedup 1.0000x reference)
#include <cuda_runtime.h>
#include <math.h>

// ---------------- problem constants ----------------
#define PAD_TOK 0
#define SOS_TOK 1
#define EOS_TOK 2
#define VOCAB   50000
#define EMB     512
#define HID     1024
#define OUTC    5

// ---------------- kernel geometry ----------------
#define NBLK   128          // persistent CTAs (<= 148 SMs, occupancy 1 -> all resident)
#define UNITS  8            // hidden units per CTA (128*8 = 1024)
#define ROWS   32           // 4 gates * UNITS rows of the fused [4096 x 1536] weight
#define KTOT   (EMB + HID)  // 1536
#define K4     (KTOT / 4)   // 384 float4 per row
#define NTH    256

// smem: ws[ROWS*KTOT] + xh[KTOT] + gs[ROWS] + bs[ROWS] + cs[UNITS] + pred[OUTC] + nid
#define SMEM_FLOATS (ROWS*KTOT + KTOT + ROWS + ROWS + UNITS + OUTC + 4)
#define SMEM_BYTES  (SMEM_FLOATS * 4)

// ---------------- global state (device scratch; no allocations) ----------------
__device__ __align__(16) float g_h[2][HID];
__device__ __align__(16) float g_cur_emb[EMB];
__device__ int g_done;
__device__ unsigned g_bar_count = 0;
__device__ volatile unsigned g_bar_gen = 0;

// ---------------- grid barrier (sense via monotonically increasing generation) ----
__device__ __forceinline__ void grid_barrier() {
    __syncthreads();
    if (threadIdx.x == 0) {
        __threadfence();
        unsigned gen = g_bar_gen;
        if (atomicAdd(&g_bar_count, 1u) == (unsigned)(NBLK - 1)) {
            g_bar_count = 0u;
            __threadfence();
            g_bar_gen = gen + 1u;
        } else {
            while (g_bar_gen == gen) { /* spin (volatile -> bypasses L1) */ }
        }
        __threadfence();
    }
    __syncthreads();
}

__device__ __forceinline__ float sigmoidf_(float x) { return 1.0f / (1.0f + expf(-x)); }

// ---------------- load 32 fused weight rows into smem ----------------
// row r = q*UNITS + u  (q = gate 0..3 in i,f,g,o order; u = local unit)
// global gate row G = q*HID + b*UNITS + u ; fused row = [Wih[G][0:512] | Whh[G][0:1024]]
__device__ void load_weights(const float* __restrict__ Wih, const float* __restrict__ Whh,
                             const float* __restrict__ bih, const float* __restrict__ bhh,
                             float* ws, float* bs, int b)
{
    const int tid = threadIdx.x;
    for (int idx = tid; idx < ROWS * K4; idx += NTH) {
        int r = idx / K4;
        int c = idx - r * K4;
        int q = r >> 3, u = r & 7;
        size_t G = (size_t)q * HID + (size_t)b * UNITS + u;
        float4 v;
        if (c < EMB / 4) v = ((const float4*)(Wih + G * EMB))[c];
        else             v = ((const float4*)(Whh + G * HID))[c - EMB / 4];
        ((float4*)(ws + (size_t)r * KTOT))[c] = v;
    }
    if (tid < ROWS) {
        int q = tid >> 3, u = tid & 7;
        size_t G = (size_t)q * HID + (size_t)b * UNITS + u;
        bs[tid] = bih[G] + bhh[G];
    }
}

// ---------------- 32-row fused GEMV from smem: gs[r] = ws[r,:] . xh + bs[r] ----------
__device__ __forceinline__ void compute_gates(const float* ws, const float* xh,
                                              const float* bs, float* gs)
{
    const int warp = threadIdx.x >> 5;
    const int lane = threadIdx.x & 31;
    const int r0 = warp * 4;
    const float4* w0 = (const float4*)(ws + (size_t)(r0 + 0) * KTOT);
    const float4* w1 = (const float4*)(ws + (size_t)(r0 + 1) * KTOT);
    const float4* w2 = (const float4*)(ws + (size_t)(r0 + 2) * KTOT);
    const float4* w3 = (const float4*)(ws + (size_t)(r0 + 3) * KTOT);
    const float4* v4 = (const float4*)xh;
    float a0 = 0.f, a1 = 0.f, a2 = 0.f, a3 = 0.f;
#pragma unroll
    for (int kk = 0; kk < K4 / 32; kk++) {
        int k = lane + kk * 32;
        float4 v = v4[k];
        float4 t0 = w0[k]; a0 += v.x * t0.x + v.y * t0.y + v.z * t0.z + v.w * t0.w;
        float4 t1 = w1[k]; a1 += v.x * t1.x + v.y * t1.y + v.z * t1.z + v.w * t1.w;
        float4 t2 = w2[k]; a2 += v.x * t2.x + v.y * t2.y + v.z * t2.z + v.w * t2.w;
        float4 t3 = w3[k]; a3 += v.x * t3.x + v.y * t3.y + v.z * t3.z + v.w * t3.w;
    }
#pragma unroll
    for (int off = 16; off > 0; off >>= 1) {
        a0 += __shfl_xor_sync(0xffffffffu, a0, off);
        a1 += __shfl_xor_sync(0xffffffffu, a1, off);
        a2 += __shfl_xor_sync(0xffffffffu, a2, off);
        a3 += __shfl_xor_sync(0xffffffffu, a3, off);
    }
    if (lane == 0) {
        gs[r0 + 0] = a0 + bs[r0 + 0];
        gs[r0 + 1] = a1 + bs[r0 + 1];
        gs[r0 + 2] = a2 + bs[r0 + 2];
        gs[r0 + 3] = a3 + bs[r0 + 3];
    }
}

__global__ void __launch_bounds__(NTH, 1)
seq2seq_kernel(const int* __restrict__ x_ids, int seq,
               const float* __restrict__ emb,
               const float* __restrict__ eWih, const float* __restrict__ eWhh,
               const float* __restrict__ ebih, const float* __restrict__ ebhh,
               const float* __restrict__ dWih, const float* __restrict__ dWhh,
               const float* __restrict__ dbih, const float* __restrict__ dbhh,
               const float* __restrict__ outW, const float* __restrict__ outb,
               const int* __restrict__ maxlen_p,
               float* __restrict__ out, int out_size)
{
    extern __shared__ float sm[];
    float* ws     = sm;                    // ROWS*KTOT
    float* xh     = ws + ROWS * KTOT;      // KTOT
    float* gs     = xh + KTOT;             // ROWS
    float* bs     = gs + ROWS;             // ROWS
    float* cs     = bs + ROWS;             // UNITS (cell state lives here across steps)
    float* pred_s = cs + UNITS;            // OUTC
    int*   nid_s  = (int*)(pred_s + OUTC);

    const int tid = threadIdx.x;
    const int b   = blockIdx.x;
    const int warp = tid >> 5, lane = tid & 31;

    // ---- phase 0: load encoder weights + init state ----
    load_weights(eWih, eWhh, ebih, ebhh, ws, bs, b);
    if (tid < UNITS) {
        cs[tid] = 0.0f;
        g_h[0][b * UNITS + tid] = 0.0f;
    }
    if (b == 0) {
        for (int k = tid; k < out_size; k += NTH) out[k] = 0.0f;
        for (int k = tid; k < EMB; k += NTH) g_cur_emb[k] = emb[(size_t)SOS_TOK * EMB + k];
        if (tid == 0) g_done = 0;
    }
    __threadfence();
    grid_barrier();

    // ---- phase 1: encoder recurrence ----
    for (int t = 0; t < seq; t++) {
        int tok = x_ids[t];                                   // emb row PAD is already zero
        const float4* e4 = (const float4*)(emb + (size_t)tok * EMB);
        const float4* h4 = (const float4*)(g_h[t & 1]);
        float4* xh4 = (float4*)xh;
        if (tid < EMB / 4) xh4[tid] = e4[tid];
        xh4[EMB / 4 + tid] = __ldcg(h4 + tid);                // cross-SM data: bypass L1
        __syncthreads();

        compute_gates(ws, xh, bs, gs);
        __syncthreads();

        if (tid < UNITS) {
            float gi = gs[tid], gf = gs[8 + tid], gg = gs[16 + tid], go = gs[24 + tid];
            float c = cs[tid];
            float cn = sigmoidf_(gf) * c + sigmoidf_(gi) * tanhf(gg);
            float hn = sigmoidf_(go) * tanhf(cn);
            cs[tid] = cn;
            g_h[(t + 1) & 1][b * UNITS + tid] = hn;
            __threadfence();                                  // release before barrier
        }
        grid_barrier();
    }

    // ---- phase 2: swap in decoder weights (CTA-local, no grid sync needed) ----
    load_weights(dWih, dWhh, dbih, dbhh, ws, bs, b);
    __syncthreads();

    const int maxlen = *maxlen_p;

    // ---- phase 3: greedy decoder ----
    for (int d = 0; d < maxlen; d++) {
        if (__ldcg(&g_done)) break;                           // consistent across CTAs (post-barrier)
        int p = (seq + d) & 1;
        const float4* e4 = (const float4*)g_cur_emb;
        const float4* h4 = (const float4*)(g_h[p]);
        float4* xh4 = (float4*)xh;
        if (tid < EMB / 4) xh4[tid] = __ldcg(e4 + tid);
        xh4[EMB / 4 + tid] = __ldcg(h4 + tid);
        __syncthreads();

        compute_gates(ws, xh, bs, gs);
        __syncthreads();

        if (tid < UNITS) {
            float gi = gs[tid], gf = gs[8 + tid], gg = gs[16 + tid], go = gs[24 + tid];
            float c = cs[tid];
            float cn = sigmoidf_(gf) * c + sigmoidf_(gi) * tanhf(gg);
            float hn = sigmoidf_(go) * tanhf(cn);
            cs[tid] = cn;
            g_h[p ^ 1][b * UNITS + tid] = hn;
            __threadfence();
        }
        grid_barrier();

        // block 0: output projection, greedy token, feedback embedding
        if (b == 0) {
            if (warp < OUTC) {
                const float* hrow = g_h[p ^ 1];
                float a = 0.0f;
                for (int k = lane; k < HID; k += 32)
                    a += __ldcg(hrow + k) * outW[(size_t)warp * HID + k];
#pragma unroll
                for (int off = 16; off > 0; off >>= 1)
                    a += __shfl_xor_sync(0xffffffffu, a, off);
                if (lane == 0) pred_s[warp] = a + outb[warp];
            }
            __syncthreads();
            if (tid == 0) {
                for (int o = 0; o < OUTC; o++) out[d * OUTC + o] = pred_s[o];
                if (out_size >= maxlen * OUTC + maxlen)
                    out[maxlen * OUTC + d] = 1.0f;            // valids[d]
                float r = rintf(pred_s[0]);                   // round-half-to-even, like jnp.round
                r = fminf(fmaxf(r, 0.0f), (float)(VOCAB - 1));
                int nid = (int)r;
                *nid_s = nid;
                if (nid == EOS_TOK) g_done = 1;
            }
            __syncthreads();
            int nid = *nid_s;
            float sc = (nid != PAD_TOK) ? 1.0f : 0.0f;
            for (int k = tid; k < EMB; k += NTH)
                g_cur_emb[k] = emb[(size_t)nid * EMB + k] * sc;
            __threadfence();
        }
        grid_barrier();
    }
}

extern "C" void kernel_launch(void* const* d_in, const int* in_sizes, int n_in,
                              void* d_out, int out_size)
{
    const int*   x     = (const int*)  d_in[0];
    const float* emb   = (const float*)d_in[1];
    const float* eWih  = (const float*)d_in[2];
    const float* eWhh  = (const float*)d_in[3];
    const float* ebih  = (const float*)d_in[4];
    const float* ebhh  = (const float*)d_in[5];
    const float* dWih  = (const float*)d_in[6];
    const float* dWhh  = (const float*)d_in[7];
    const float* dbih  = (const float*)d_in[8];
    const float* dbhh  = (const float*)d_in[9];
    const float* outW  = (const float*)d_in[10];
    const float* outb  = (const float*)d_in[11];
    const int*   mlp   = (const int*)  d_in[12];
    int seq = in_sizes[0];

    cudaFuncSetAttribute(seq2seq_kernel,
                         cudaFuncAttributeMaxDynamicSharedMemorySize, SMEM_BYTES);

    seq2seq_kernel<<<NBLK, NTH, SMEM_BYTES>>>(
        x, seq, emb, eWih, eWhh, ebih, ebhh,
        dWih, dWhh, dbih, dbhh, outW, outb, mlp,
        (float*)d_out, out_size);
}

// round 2
// speedup vs baseline: 1.1442x; 1.1442x over previous
#include <cuda_runtime.h>
#include <math.h>

// ---------------- problem constants ----------------
#define PAD_TOK 0
#define SOS_TOK 1
#define EOS_TOK 2
#define VOCAB   50000
#define EMB     512
#define HID     1024
#define OUTC    5

// ---------------- kernel geometry ----------------
#define NBLK   128          // persistent CTAs (<=148 SMs, all co-resident)
#define NTH    256
#define UNITS  8            // hidden units per CTA
#define ROWS   32           // 4 gates * UNITS
#define KTOT   (EMB + HID)  // 1536
#define NJ     48           // k-chunks per lane stripe (48*32 = 1536)
#define XJ     16           // j < XJ  -> x (embedding) part of the fused K

// ---------------- global state (static device scratch) ----------------
__device__ __align__(16) float g_h[2][HID];
__device__ __align__(16) float g_cur_emb[EMB];
__device__ int g_done;
__device__ unsigned g_bar_count;          // zero-init; returns to 0 after each full barrier
__device__ volatile unsigned g_bar_gen;   // monotonically increasing across graph replays

// ---- split grid barrier: arrive (any thread) / wait (target generation) ----
__device__ __forceinline__ void bar_arrive() {
    __threadfence();
    if (atomicAdd(&g_bar_count, 1u) == (unsigned)(NBLK - 1)) {
        g_bar_count = 0u;
        __threadfence();
        g_bar_gen = g_bar_gen + 1u;
    }
}
__device__ __forceinline__ void bar_wait(unsigned target) {
    while (g_bar_gen < target) { /* spin; volatile -> L2 */ }
    __threadfence();
}

__device__ __forceinline__ float sigmoidf_(float x) { return 1.0f / (1.0f + expf(-x)); }

// ---------------- load this thread's register weight stripe ----------------
// warp owns CTA-local rows r = warp*4 + i (i=0..3); r -> gate q=r>>3, unit u=r&7
// global gate row G = q*HID + b*UNITS + u
// fused k: [0,512) = Wih columns, [512,1536) = Whh columns; lane stripe k = j*32+lane
__device__ __forceinline__ void load_wregs(
    const float* __restrict__ Wih, const float* __restrict__ Whh,
    const float* __restrict__ bih, const float* __restrict__ bhh,
    float (&w)[4][NJ], float* bs, int b, int warp, int lane, int tid)
{
#pragma unroll
    for (int i = 0; i < 4; i++) {
        int r = warp * 4 + i, q = r >> 3, u = r & 7;
        size_t G = (size_t)q * HID + (size_t)b * UNITS + u;
        const float* rx = Wih + G * EMB;
        const float* rh = Whh + G * HID;
#pragma unroll
        for (int j = 0; j < XJ; j++)  w[i][j] = rx[j * 32 + lane];
#pragma unroll
        for (int j = XJ; j < NJ; j++) w[i][j] = rh[(j - XJ) * 32 + lane];
    }
    if (tid < ROWS) {
        int q = tid >> 3, u = tid & 7;
        size_t G = (size_t)q * HID + (size_t)b * UNITS + u;
        bs[tid] = bih[G] + bhh[G];
    }
}

// ---------------- register-weight MAC over j-range [J0,J1) ----------------
template <int J0, int J1>
__device__ __forceinline__ void mac(const float (&w)[4][NJ], const float* xh, int lane,
                                    float& a0, float& a1, float& a2, float& a3)
{
#pragma unroll
    for (int j = J0; j < J1; j++) {
        float v = xh[j * 32 + lane];           // conflict-free LDS.32
        a0 = fmaf(v, w[0][j], a0);
        a1 = fmaf(v, w[1][j], a1);
        a2 = fmaf(v, w[2][j], a2);
        a3 = fmaf(v, w[3][j], a3);
    }
}

__device__ __forceinline__ void reduce_store(float a0, float a1, float a2, float a3,
                                             float* gs, const float* bs, int warp, int lane)
{
#pragma unroll
    for (int off = 16; off; off >>= 1) {
        a0 += __shfl_xor_sync(0xffffffffu, a0, off);
        a1 += __shfl_xor_sync(0xffffffffu, a1, off);
        a2 += __shfl_xor_sync(0xffffffffu, a2, off);
        a3 += __shfl_xor_sync(0xffffffffu, a3, off);
    }
    if (lane == 0) {
        int r = warp * 4;
        gs[r + 0] = a0 + bs[r + 0];
        gs[r + 1] = a1 + bs[r + 1];
        gs[r + 2] = a2 + bs[r + 2];
        gs[r + 3] = a3 + bs[r + 3];
    }
}

__global__ void __launch_bounds__(NTH, 1)
seq2seq_kernel(const int* __restrict__ x_ids, int seq,
               const float* __restrict__ emb,
               const float* __restrict__ eWih, const float* __restrict__ eWhh,
               const float* __restrict__ ebih, const float* __restrict__ ebhh,
               const float* __restrict__ dWih, const float* __restrict__ dWhh,
               const float* __restrict__ dbih, const float* __restrict__ dbhh,
               const float* __restrict__ outW, const float* __restrict__ outb,
               const int* __restrict__ maxlen_p,
               float* __restrict__ out, int out_size)
{
    __shared__ float xh[KTOT];
    __shared__ float gs[ROWS];
    __shared__ float bs[ROWS];
    __shared__ float cs[UNITS];
    __shared__ float pred_s[OUTC];
    __shared__ int   nid_s;

    const int tid = threadIdx.x;
    const int b = blockIdx.x;
    const int warp = tid >> 5, lane = tid & 31;

    // barrier base generation (stable: previous replay fully completed)
    unsigned bar_base = 0;
    if (tid == 0) bar_base = g_bar_gen;
    unsigned epoch = 0;

    // ---- phase 0: encoder weights -> registers; init state ----
    float w[4][NJ];
    load_wregs(eWih, eWhh, ebih, ebhh, w, bs, b, warp, lane, tid);
    if (tid < UNITS) {
        cs[tid] = 0.0f;
        g_h[0][b * UNITS + tid] = 0.0f;
    }
    if (b == 0) {
        for (int k = tid; k < out_size; k += NTH) out[k] = 0.0f;
        if (tid < EMB / 4)
            ((float4*)g_cur_emb)[tid] = ((const float4*)(emb + (size_t)SOS_TOK * EMB))[tid];
        if (tid == 0) g_done = 0;
    }
    __threadfence();
    __syncthreads();
    if (tid == 32) bar_arrive();
    epoch = 1;

    // ---- phase 1: encoder (x-part computed before waiting on h_t) ----
    for (int t = 0; t < seq; t++) {
        int tok = x_ids[t];                          // PAD row of emb is zero
        if (tid < EMB / 4)
            ((float4*)xh)[tid] = ((const float4*)(emb + (size_t)tok * EMB))[tid];
        __syncthreads();

        float a0 = 0.f, a1 = 0.f, a2 = 0.f, a3 = 0.f;
        mac<0, XJ>(w, xh, lane, a0, a1, a2, a3);     // overlaps barrier latency

        if (tid == 0) bar_wait(bar_base + epoch);    // h_t published
        __syncthreads();
        ((float4*)xh)[EMB / 4 + tid] = __ldcg(((const float4*)(g_h[t & 1])) + tid);
        __syncthreads();

        mac<XJ, NJ>(w, xh, lane, a0, a1, a2, a3);
        reduce_store(a0, a1, a2, a3, gs, bs, warp, lane);
        __syncthreads();

        if (tid < UNITS) {
            float gi = gs[tid], gf = gs[8 + tid], gg = gs[16 + tid], go = gs[24 + tid];
            float c = cs[tid];
            float cn = sigmoidf_(gf) * c + sigmoidf_(gi) * tanhf(gg);
            float hn = sigmoidf_(go) * tanhf(cn);
            cs[tid] = cn;
            g_h[(t + 1) & 1][b * UNITS + tid] = hn;
            __threadfence();
        }
        __syncthreads();
        if (tid == 32) bar_arrive();
        epoch++;
    }

    // ---- phase 2: decoder weights -> registers ----
    load_wregs(dWih, dWhh, dbih, dbhh, w, bs, b, warp, lane, tid);
    const int maxlen = *maxlen_p;

    // ---- phase 3: greedy decoder ----
    for (int d = 0; d < maxlen; d++) {
        if (tid == 0) bar_wait(bar_base + epoch);    // h_d and emb_d published
        __syncthreads();
        if (__ldcg(&g_done)) break;                  // consistent across CTAs

        int p = (seq + d) & 1;
        if (tid < EMB / 4)
            ((float4*)xh)[tid] = __ldcg(((const float4*)g_cur_emb) + tid);
        ((float4*)xh)[EMB / 4 + tid] = __ldcg(((const float4*)(g_h[p])) + tid);
        __syncthreads();

        float a0 = 0.f, a1 = 0.f, a2 = 0.f, a3 = 0.f;
        mac<0, NJ>(w, xh, lane, a0, a1, a2, a3);
        reduce_store(a0, a1, a2, a3, gs, bs, warp, lane);
        __syncthreads();

        if (tid < UNITS) {
            float gi = gs[tid], gf = gs[8 + tid], gg = gs[16 + tid], go = gs[24 + tid];
            float c = cs[tid];
            float cn = sigmoidf_(gf) * c + sigmoidf_(gi) * tanhf(gg);
            float hn = sigmoidf_(go) * tanhf(cn);
            cs[tid] = cn;
            g_h[p ^ 1][b * UNITS + tid] = hn;
            __threadfence();
        }
        __syncthreads();
        if (tid == 32) bar_arrive();
        epoch++;

        if (tid == 0) bar_wait(bar_base + epoch);    // h_{d+1} visible to block 0
        __syncthreads();

        if (b == 0) {
            if (warp < OUTC) {
                const float* hrow = g_h[p ^ 1];
                float a = 0.0f;
                for (int k = lane; k < HID; k += 32)
                    a += __ldcg(hrow + k) * outW[(size_t)warp * HID + k];
#pragma unroll
                for (int off = 16; off; off >>= 1)
                    a += __shfl_xor_sync(0xffffffffu, a, off);
                if (lane == 0) pred_s[warp] = a + outb[warp];
            }
            __syncthreads();
            if (tid == 0) {
                for (int o = 0; o < OUTC; o++) out[d * OUTC + o] = pred_s[o];
                if (maxlen * OUTC + d < out_size) out[maxlen * OUTC + d] = 1.0f;  // valids[d]
                float r = rintf(pred_s[0]);          // half-to-even like jnp.round
                r = fminf(fmaxf(r, 0.0f), (float)(VOCAB - 1));
                int nid = (int)r;
                nid_s = nid;
                if (nid == EOS_TOK) g_done = 1;
            }
            __syncthreads();
            int nid = nid_s;
            float sc = (nid != PAD_TOK) ? 1.0f : 0.0f;
            for (int k = tid; k < EMB; k += NTH)
                g_cur_emb[k] = emb[(size_t)nid * EMB + k] * sc;
            __threadfence();
        }
        __syncthreads();
        if (tid == 32) bar_arrive();
        epoch++;
    }
}

extern "C" void kernel_launch(void* const* d_in, const int* in_sizes, int n_in,
                              void* d_out, int out_size)
{
    const int*   x    = (const int*)  d_in[0];
    const float* emb  = (const float*)d_in[1];
    const float* eWih = (const float*)d_in[2];
    const float* eWhh = (const float*)d_in[3];
    const float* ebih = (const float*)d_in[4];
    const float* ebhh = (const float*)d_in[5];
    const float* dWih = (const float*)d_in[6];
    const float* dWhh = (const float*)d_in[7];
    const float* dbih = (const float*)d_in[8];
    const float* dbhh = (const float*)d_in[9];
    const float* outW = (const float*)d_in[10];
    const float* outb = (const float*)d_in[11];
    const int*   mlp  = (const int*)  d_in[12];
    int seq = in_sizes[0];

    seq2seq_kernel<<<NBLK, NTH>>>(
        x, seq, emb, eWih, eWhh, ebih, ebhh,
        dWih, dWhh, dbih, dbhh, outW, outb, mlp,
        (float*)d_out, out_size);
}

// round 3
// speedup vs baseline: 1.3478x; 1.1780x over previous
#include <cuda_runtime.h>
#include <math.h>

// ---------------- problem constants ----------------
#define PAD_TOK 0
#define SOS_TOK 1
#define EOS_TOK 2
#define VOCAB   50000
#define EMB     512
#define HID     1024
#define OUTC    5

// ---------------- kernel geometry ----------------
#define NBLK   128          // persistent CTAs, all co-resident
#define NTH    256
#define UNITS  8            // hidden units per CTA
#define ROWS   32           // 4 gates * UNITS
#define KTOT   (EMB + HID)  // 1536
#define NJ     48           // k-chunks per lane stripe
#define XJ     16           // j < XJ -> embedding part
#define TOKCAP 2048         // smem token cache capacity
#define FSTR   32           // flag stride in u32 (128B separation)

// ---------------- global state (static device scratch) ----------------
__device__ unsigned g_flags[NBLK * FSTR];   // per-producer h epoch flags
__device__ unsigned g_flag2[FSTR];          // block0 -> all (emb/done epoch)
__device__ __align__(16) float g_h[2][HID];
__device__ __align__(16) float g_cur_emb[EMB];
__device__ int g_done;

// ---------------- acquire/release primitives (no atomics, no fences) -------
__device__ __forceinline__ unsigned ld_acq(const unsigned* p) {
    unsigned v;
    asm volatile("ld.acquire.gpu.global.u32 %0, [%1];" : "=r"(v) : "l"(p) : "memory");
    return v;
}
__device__ __forceinline__ void st_rel(unsigned* p, unsigned v) {
    asm volatile("st.release.gpu.global.u32 [%0], %1;" :: "l"(p), "r"(v) : "memory");
}
__device__ __forceinline__ void wait_ge(const unsigned* p, unsigned tgt) {
    while ((int)(ld_acq(p) - tgt) < 0) { }
}

// ---------------- fast activations (MUFU-based) ----------------
__device__ __forceinline__ float fsig(float x) {
    return __fdividef(1.0f, 1.0f + __expf(-x));
}
__device__ __forceinline__ float ftanh(float x) {
    return 1.0f - __fdividef(2.0f, __expf(2.0f * x) + 1.0f);
}

// ---------------- register weight stripe load ----------------
// warp owns rows r = warp*4+i; r -> gate q=r>>3, unit u=r&7
// global gate row G = q*HID + b*UNITS + u ; stripe k = j*32+lane
__device__ __forceinline__ void load_wregs(
    const float* __restrict__ Wih, const float* __restrict__ Whh,
    const float* __restrict__ bih, const float* __restrict__ bhh,
    float (&w)[4][NJ], float* bs, int b, int warp, int lane, int tid)
{
#pragma unroll
    for (int i = 0; i < 4; i++) {
        int r = warp * 4 + i, q = r >> 3, u = r & 7;
        size_t G = (size_t)q * HID + (size_t)b * UNITS + u;
        const float* rx = Wih + G * EMB;
        const float* rh = Whh + G * HID;
#pragma unroll
        for (int j = 0; j < XJ; j++)  w[i][j] = rx[j * 32 + lane];
#pragma unroll
        for (int j = XJ; j < NJ; j++) w[i][j] = rh[(j - XJ) * 32 + lane];
    }
    if (tid < ROWS) {
        int q = tid >> 3, u = tid & 7;
        size_t G = (size_t)q * HID + (size_t)b * UNITS + u;
        bs[tid] = bih[G] + bhh[G];
    }
}

template <int J0, int J1>
__device__ __forceinline__ void mac(const float (&w)[4][NJ], const float* xh, int lane,
                                    float& a0, float& a1, float& a2, float& a3)
{
#pragma unroll
    for (int j = J0; j < J1; j++) {
        float v = xh[j * 32 + lane];
        a0 = fmaf(v, w[0][j], a0);
        a1 = fmaf(v, w[1][j], a1);
        a2 = fmaf(v, w[2][j], a2);
        a3 = fmaf(v, w[3][j], a3);
    }
}

__device__ __forceinline__ void reduce_store(float a0, float a1, float a2, float a3,
                                             float* gs, const float* bs, int warp, int lane)
{
#pragma unroll
    for (int off = 16; off; off >>= 1) {
        a0 += __shfl_xor_sync(0xffffffffu, a0, off);
        a1 += __shfl_xor_sync(0xffffffffu, a1, off);
        a2 += __shfl_xor_sync(0xffffffffu, a2, off);
        a3 += __shfl_xor_sync(0xffffffffu, a3, off);
    }
    if (lane == 0) {
        int r = warp * 4;
        gs[r + 0] = a0 + bs[r + 0];
        gs[r + 1] = a1 + bs[r + 1];
        gs[r + 2] = a2 + bs[r + 2];
        gs[r + 3] = a3 + bs[r + 3];
    }
}

__global__ void __launch_bounds__(NTH, 1)
seq2seq_kernel(const int* __restrict__ x_ids, int seq,
               const float* __restrict__ emb,
               const float* __restrict__ eWih, const float* __restrict__ eWhh,
               const float* __restrict__ ebih, const float* __restrict__ ebhh,
               const float* __restrict__ dWih, const float* __restrict__ dWhh,
               const float* __restrict__ dbih, const float* __restrict__ dbhh,
               const float* __restrict__ outW, const float* __restrict__ outb,
               const int* __restrict__ maxlen_p,
               float* __restrict__ out, int out_size)
{
    __shared__ float xh[KTOT];
    __shared__ float gs[ROWS];
    __shared__ float bs[ROWS];
    __shared__ float cs[UNITS];
    __shared__ float hs[UNITS];
    __shared__ float pred_s[OUTC];
    __shared__ int   nid_s;
    __shared__ int   done_s;
    __shared__ unsigned sbase;
    __shared__ int x_tok[TOKCAP];

    const int tid = threadIdx.x;
    const int b = blockIdx.x;
    const int warp = tid >> 5, lane = tid & 31;

    // ---- phase 0 ----
    if (tid == 0) sbase = __ldcg(&g_flags[b * FSTR]);   // own flag: exact base
    float w[4][NJ];
    load_wregs(eWih, eWhh, ebih, ebhh, w, bs, b, warp, lane, tid);
    if (tid < UNITS) cs[tid] = 0.0f;
    for (int k = tid; k < seq && k < TOKCAP; k += NTH) x_tok[k] = x_ids[k];
    __syncthreads();
    const unsigned base = sbase;

    if (tid == 0) {                                     // publish h_0 = 0
        float4 z = make_float4(0.f, 0.f, 0.f, 0.f);
        float4* dst = (float4*)(g_h[0] + b * UNITS);
        __stcg(dst, z); __stcg(dst + 1, z);
        st_rel(&g_flags[b * FSTR], base + 1);
    }
    if (b == 0) {                                       // publish emb_0 / done_0
        for (int k = tid; k < out_size; k += NTH) out[k] = 0.0f;
        if (tid < EMB / 4)
            ((float4*)g_cur_emb)[tid] = ((const float4*)(emb + (size_t)SOS_TOK * EMB))[tid];
        if (tid == 0) g_done = 0;
        __syncthreads();
        if (tid == 0) st_rel(&g_flag2[0], base + 1 + (unsigned)seq);
    }

    // preload embedding row for t=0
    float4 epf = make_float4(0.f, 0.f, 0.f, 0.f);
    if (tid < 128 && seq > 0) {
        int tok0 = x_tok[0];
        epf = ((const float4*)(emb + (size_t)tok0 * EMB))[tid];
    }

    // ---- phase 1: encoder ----
    for (int t = 0; t < seq; t++) {
        if (tid < 128) ((float4*)xh)[tid] = epf;        // prefetched x_t
        __syncthreads();

        float a0 = 0.f, a1 = 0.f, a2 = 0.f, a3 = 0.f;
        mac<0, XJ>(w, xh, lane, a0, a1, a2, a3);

        if (tid < 128) {
            // issue next-step embedding prefetch (independent of h)
            if (t + 1 < seq) {
                int tk = (t + 1 < TOKCAP) ? x_tok[t + 1] : x_ids[t + 1];
                epf = ((const float4*)(emb + (size_t)tk * EMB))[tid];
            }
            // wait on producer tid's flag, then pull its h chunk
            wait_ge(&g_flags[tid * FSTR], base + 1 + (unsigned)t);
            const float4* hp = (const float4*)(g_h[t & 1] + tid * UNITS);
            float4 v0 = __ldcg(hp), v1 = __ldcg(hp + 1);
            ((float4*)(xh + EMB))[tid * 2 + 0] = v0;
            ((float4*)(xh + EMB))[tid * 2 + 1] = v1;
        }
        __syncthreads();

        mac<XJ, NJ>(w, xh, lane, a0, a1, a2, a3);
        reduce_store(a0, a1, a2, a3, gs, bs, warp, lane);
        __syncthreads();

        if (tid < UNITS) {
            float gi = gs[tid], gf = gs[8 + tid], gg = gs[16 + tid], go = gs[24 + tid];
            float c = cs[tid];
            float cn = fsig(gf) * c + fsig(gi) * ftanh(gg);
            float hn = fsig(go) * ftanh(cn);
            cs[tid] = cn;
            hs[tid] = hn;
        }
        __syncthreads();

        if (tid == 0) {
            float4 h0 = *(float4*)hs, h1 = *(float4*)(hs + 4);
            float4* dst = (float4*)(g_h[(t + 1) & 1] + b * UNITS);
            __stcg(dst, h0); __stcg(dst + 1, h1);
            st_rel(&g_flags[b * FSTR], base + 2 + (unsigned)t);
        }
    }

    // ---- phase 2: decoder weights ----
    load_wregs(dWih, dWhh, dbih, dbhh, w, bs, b, warp, lane, tid);
    const int maxlen = *maxlen_p;

    // ---- phase 3: greedy decoder ----
    for (int d = 0; d < maxlen; d++) {
        const unsigned eh = base + 1 + (unsigned)(seq + d);   // h_{seq+d} + emb_d epoch
        if (tid == 0) {
            wait_ge(&g_flag2[0], eh);
            done_s = __ldcg(&g_done);
        }
        __syncthreads();
        if (done_s) break;

        int p = (seq + d) & 1;
        if (tid < 128) {
            ((float4*)xh)[tid] = __ldcg(((const float4*)g_cur_emb) + tid);
            wait_ge(&g_flags[tid * FSTR], eh);
            const float4* hp = (const float4*)(g_h[p] + tid * UNITS);
            float4 v0 = __ldcg(hp), v1 = __ldcg(hp + 1);
            ((float4*)(xh + EMB))[tid * 2 + 0] = v0;
            ((float4*)(xh + EMB))[tid * 2 + 1] = v1;
        }
        __syncthreads();

        float a0 = 0.f, a1 = 0.f, a2 = 0.f, a3 = 0.f;
        mac<0, NJ>(w, xh, lane, a0, a1, a2, a3);
        reduce_store(a0, a1, a2, a3, gs, bs, warp, lane);
        __syncthreads();

        if (tid < UNITS) {
            float gi = gs[tid], gf = gs[8 + tid], gg = gs[16 + tid], go = gs[24 + tid];
            float c = cs[tid];
            float cn = fsig(gf) * c + fsig(gi) * ftanh(gg);
            float hn = fsig(go) * ftanh(cn);
            cs[tid] = cn;
            hs[tid] = hn;
        }
        __syncthreads();

        if (tid == 0) {
            float4 h0 = *(float4*)hs, h1 = *(float4*)(hs + 4);
            float4* dst = (float4*)(g_h[p ^ 1] + b * UNITS);
            __stcg(dst, h0); __stcg(dst + 1, h1);
            st_rel(&g_flags[b * FSTR], eh + 1);
        }

        // block 0: projection, greedy token, publish emb/done for step d+1
        if (b == 0) {
            if (tid < 128) wait_ge(&g_flags[tid * FSTR], eh + 1);
            __syncthreads();
            if (warp < OUTC) {
                const float* hrow = g_h[p ^ 1];
                float a = 0.0f;
                for (int k = lane; k < HID; k += 32)
                    a += __ldcg(hrow + k) * outW[(size_t)warp * HID + k];
#pragma unroll
                for (int off = 16; off; off >>= 1)
                    a += __shfl_xor_sync(0xffffffffu, a, off);
                if (lane == 0) pred_s[warp] = a + outb[warp];
            }
            __syncthreads();
            if (tid == 0) {
                for (int o = 0; o < OUTC; o++) out[d * OUTC + o] = pred_s[o];
                if (maxlen * OUTC + d < out_size) out[maxlen * OUTC + d] = 1.0f;  // valid
                float r = rintf(pred_s[0]);                 // half-to-even like jnp.round
                r = fminf(fmaxf(r, 0.0f), (float)(VOCAB - 1));
                int nid = (int)r;
                nid_s = nid;
                if (nid == EOS_TOK) g_done = 1;
            }
            __syncthreads();
            int nid = nid_s;
            float sc = (nid != PAD_TOK) ? 1.0f : 0.0f;
            for (int k = tid; k < EMB; k += NTH)
                g_cur_emb[k] = emb[(size_t)nid * EMB + k] * sc;
            __syncthreads();
            if (tid == 0) st_rel(&g_flag2[0], eh + 1);
        }
    }
}

extern "C" void kernel_launch(void* const* d_in, const int* in_sizes, int n_in,
                              void* d_out, int out_size)
{
    const int*   x    = (const int*)  d_in[0];
    const float* emb  = (const float*)d_in[1];
    const float* eWih = (const float*)d_in[2];
    const float* eWhh = (const float*)d_in[3];
    const float* ebih = (const float*)d_in[4];
    const float* ebhh = (const float*)d_in[5];
    const float* dWih = (const float*)d_in[6];
    const float* dWhh = (const float*)d_in[7];
    const float* dbih = (const float*)d_in[8];
    const float* dbhh = (const float*)d_in[9];
    const float* outW = (const float*)d_in[10];
    const float* outb = (const float*)d_in[11];
    const int*   mlp  = (const int*)  d_in[12];
    int seq = in_sizes[0];

    seq2seq_kernel<<<NBLK, NTH>>>(
        x, seq, emb, eWih, eWhh, ebih, ebhh,
        dWih, dWhh, dbih, dbhh, outW, outb, mlp,
        (float*)d_out, out_size);
}

// round 4
// speedup vs baseline: 1.5899x; 1.1796x over previous
#include <cuda_runtime.h>
#include <math.h>

// ---------------- problem constants ----------------
#define PAD_TOK 0
#define SOS_TOK 1
#define EOS_TOK 2
#define VOCAB   50000
#define EMB     512
#define HID     1024
#define OUTC    5

// ---------------- kernel geometry ----------------
#define NBLK   128          // persistent CTAs, all co-resident
#define NTH    256
#define UNITS  8            // hidden units per CTA (warp u owns unit u)
#define KTOT   (EMB + HID)  // 1536
#define NJ64   24           // float2 chunks: k = j*64 + lane*2
#define XJ64   8            // j < XJ64 -> embedding part (k < 512)
#define JR     20           // j < JR in registers; [JR,NJ64) in smem
#define WS_K0  (JR * 64)    // 1280: first k column held in smem
#define WS_KN  (KTOT - WS_K0)  // 256 floats per row in smem
#define FSTR   32           // flag stride (128B)
#define TOKCAP 2048

// ---------------- global state ----------------
__device__ unsigned g_flags[NBLK * FSTR];
__device__ unsigned g_flag2[FSTR];
__device__ __align__(16) float g_h[2][HID];
__device__ __align__(16) float g_cur_emb[EMB];
__device__ int g_done;

// ---------------- sync primitives ----------------
__device__ __forceinline__ unsigned ld_acq(const unsigned* p) {
    unsigned v;
    asm volatile("ld.acquire.gpu.global.u32 %0, [%1];" : "=r"(v) : "l"(p) : "memory");
    return v;
}
__device__ __forceinline__ void st_rel(unsigned* p, unsigned v) {
    asm volatile("st.release.gpu.global.u32 [%0], %1;" :: "l"(p), "r"(v) : "memory");
}
__device__ __forceinline__ void wait_ge(const unsigned* p, unsigned tgt) {
    while ((int)(ld_acq(p) - tgt) < 0) { }
}

// ---------------- packed dual-FMA (Blackwell f32x2) ----------------
typedef unsigned long long u64t;
__device__ __forceinline__ void fma2(u64t& d, u64t a, u64t b) {
    asm("fma.rn.f32x2 %0, %1, %2, %0;" : "+l"(d) : "l"(a), "l"(b));
}
__device__ __forceinline__ float f2lo(u64t v) { return __uint_as_float((unsigned)v); }
__device__ __forceinline__ float f2hi(u64t v) { return __uint_as_float((unsigned)(v >> 32)); }

// ---------------- fast activations (proven accurate in r3) ----------------
__device__ __forceinline__ float fsig(float x)  { return __fdividef(1.0f, 1.0f + __expf(-x)); }
__device__ __forceinline__ float ftanh(float x) { return 1.0f - __fdividef(2.0f, __expf(2.0f * x) + 1.0f); }

// ---------------- smem plan (dynamic) ----------------
struct SM {
    float xh[KTOT];
    float ws[32 * WS_KN];      // weight tail, rows r = q*8+u
    int   x_tok[TOKCAP];
    float pred[OUTC];
    int   nid;
    int   done;
    unsigned sbase;
};

// ---------------- weight load: regs (j<JR) + smem tail ----------------
// warp u owns rows {q*8+u : q=0..3} = gates i,f,g,o of unit u
__device__ __forceinline__ void load_w(
    const float* __restrict__ Wih, const float* __restrict__ Whh,
    const float* __restrict__ bih, const float* __restrict__ bhh,
    u64t (&wr)[4][JR], float* ws, float (&bias)[4],
    int b, int u, int lane, int tid)
{
#pragma unroll
    for (int q = 0; q < 4; q++) {
        size_t G = (size_t)q * HID + (size_t)b * UNITS + u;
        const float* rx = Wih + G * EMB;
        const float* rh = Whh + G * HID;
#pragma unroll
        for (int j = 0; j < XJ64; j++)
            wr[q][j] = *(const u64t*)(rx + j * 64 + lane * 2);
#pragma unroll
        for (int j = XJ64; j < JR; j++)
            wr[q][j] = *(const u64t*)(rh + (j - XJ64) * 64 + lane * 2);
    }
    // smem tail: rows 0..31, k in [WS_K0, KTOT) -> Whh cols [WS_K0-EMB, HID)
    for (int i = tid; i < 32 * (WS_KN / 4); i += NTH) {
        int r = i >> 6, c = i & 63;
        int q = r >> 3, uu = r & 7;
        size_t G = (size_t)q * HID + (size_t)b * UNITS + uu;
        ((float4*)(ws + (size_t)r * WS_KN))[c] =
            ((const float4*)(Whh + G * HID + (WS_K0 - EMB)))[c];
    }
    if (lane == 0) {
#pragma unroll
        for (int q = 0; q < 4; q++) {
            size_t G = (size_t)q * HID + (size_t)b * UNITS + u;
            bias[q] = bih[G] + bhh[G];
        }
    }
}

template <int J0, int J1>
__device__ __forceinline__ void mac_reg(const u64t (&wr)[4][JR], const float* xh,
                                        int lane, u64t (&acc)[4])
{
#pragma unroll
    for (int j = J0; j < J1; j++) {
        u64t v = *(const u64t*)(xh + j * 64 + lane * 2);   // LDS.64 conflict-free
        fma2(acc[0], wr[0][j], v);
        fma2(acc[1], wr[1][j], v);
        fma2(acc[2], wr[2][j], v);
        fma2(acc[3], wr[3][j], v);
    }
}

__device__ __forceinline__ void mac_sm(const float* ws, const float* xh,
                                       int u, int lane, u64t (&acc)[4])
{
#pragma unroll
    for (int j = JR; j < NJ64; j++) {
        u64t v = *(const u64t*)(xh + j * 64 + lane * 2);
#pragma unroll
        for (int q = 0; q < 4; q++) {
            u64t wv = *(const u64t*)(ws + (size_t)(q * 8 + u) * WS_KN
                                        + (j - JR) * 64 + lane * 2);
            fma2(acc[q], wv, v);
        }
    }
}

// reduce 4 accumulators across warp; lane0 computes gates -> (cstate, hn)
__device__ __forceinline__ float finish_unit(u64t (&acc)[4], const float (&bias)[4],
                                             int lane, float& cstate)
{
    float a0 = f2lo(acc[0]) + f2hi(acc[0]);
    float a1 = f2lo(acc[1]) + f2hi(acc[1]);
    float a2 = f2lo(acc[2]) + f2hi(acc[2]);
    float a3 = f2lo(acc[3]) + f2hi(acc[3]);
#pragma unroll
    for (int off = 16; off; off >>= 1) {
        a0 += __shfl_xor_sync(0xffffffffu, a0, off);
        a1 += __shfl_xor_sync(0xffffffffu, a1, off);
        a2 += __shfl_xor_sync(0xffffffffu, a2, off);
        a3 += __shfl_xor_sync(0xffffffffu, a3, off);
    }
    float hn = 0.0f;
    if (lane == 0) {
        float gi = a0 + bias[0], gf = a1 + bias[1];
        float gg = a2 + bias[2], go = a3 + bias[3];
        float cn = fsig(gf) * cstate + fsig(gi) * ftanh(gg);
        hn = fsig(go) * ftanh(cn);
        cstate = cn;
    }
    return hn;
}

extern __shared__ __align__(16) unsigned char smem_raw[];

__global__ void __launch_bounds__(NTH, 1)
seq2seq_kernel(const int* __restrict__ x_ids, int seq,
               const float* __restrict__ emb,
               const float* __restrict__ eWih, const float* __restrict__ eWhh,
               const float* __restrict__ ebih, const float* __restrict__ ebhh,
               const float* __restrict__ dWih, const float* __restrict__ dWhh,
               const float* __restrict__ dbih, const float* __restrict__ dbhh,
               const float* __restrict__ outW, const float* __restrict__ outb,
               const int* __restrict__ maxlen_p,
               float* __restrict__ out, int out_size)
{
    SM* s = (SM*)smem_raw;
    const int tid = threadIdx.x;
    const int b = blockIdx.x;
    const int warp = tid >> 5, lane = tid & 31;   // warp == unit u

    if (tid == 0) s->sbase = __ldcg(&g_flags[b * FSTR]);

    u64t wr[4][JR];
    float bias[4] = {0.f, 0.f, 0.f, 0.f};
    load_w(eWih, eWhh, ebih, ebhh, wr, s->ws, bias, b, warp, lane, tid);
    float cstate = 0.0f;
    for (int k = tid; k < seq && k < TOKCAP; k += NTH) s->x_tok[k] = x_ids[k];
    __syncthreads();
    const unsigned base = s->sbase;

    if (tid == 0) {                                 // publish h_0 = 0
        float4 z = make_float4(0.f, 0.f, 0.f, 0.f);
        float4* dst = (float4*)(g_h[0] + b * UNITS);
        __stcg(dst, z); __stcg(dst + 1, z);
        st_rel(&g_flags[b * FSTR], base + 1);
    }
    if (b == 0) {                                   // publish emb_0 / done_0
        for (int k = tid; k < out_size; k += NTH) out[k] = 0.0f;
        if (tid < EMB / 4)
            ((float4*)g_cur_emb)[tid] = ((const float4*)(emb + (size_t)SOS_TOK * EMB))[tid];
        if (tid == 0) g_done = 0;
        __syncthreads();
        if (tid == 0) st_rel(&g_flag2[0], base + 1 + (unsigned)seq);
    }

    // x-part of xh for t=0
    float4 epf = make_float4(0.f, 0.f, 0.f, 0.f);
    if (tid < 128 && seq > 0) {
        int tok0 = s->x_tok[0];
        epf = ((const float4*)(emb + (size_t)tok0 * EMB))[tid];
        ((float4*)s->xh)[tid] = epf;
    }
    __syncthreads();

    // ---- encoder ----
    for (int t = 0; t < seq; t++) {
        u64t acc[4] = {0ull, 0ull, 0ull, 0ull};
        mac_reg<0, XJ64>(wr, s->xh, lane, acc);       // x-part (overlaps wait)

        if (tid < 128) {
            if (t + 1 < seq) {                        // prefetch next emb row
                int tk = (t + 1 < TOKCAP) ? s->x_tok[t + 1] : __ldg(&x_ids[t + 1]);
                epf = ((const float4*)(emb + (size_t)tk * EMB))[tid];
            }
            wait_ge(&g_flags[tid * FSTR], base + 1 + (unsigned)t);
            const float4* hp = (const float4*)(g_h[t & 1] + tid * UNITS);
            float4 v0 = __ldcg(hp), v1 = __ldcg(hp + 1);
            ((float4*)(s->xh + EMB))[tid * 2 + 0] = v0;
            ((float4*)(s->xh + EMB))[tid * 2 + 1] = v1;
        }
        __syncthreads();

        mac_reg<XJ64, JR>(wr, s->xh, lane, acc);      // h-part (regs)
        mac_sm(s->ws, s->xh, warp, lane, acc);        // h-part (smem tail)
        float hn = finish_unit(acc, bias, lane, cstate);

        if (tid < 128) ((float4*)s->xh)[tid] = epf;   // stage x-part for t+1 (region dead)
        if (lane == 0) __stcg(&g_h[(t + 1) & 1][b * UNITS + warp], hn);
        __syncthreads();
        if (tid == 0) st_rel(&g_flags[b * FSTR], base + 2 + (unsigned)t);
    }

    // ---- decoder weights ----
    load_w(dWih, dWhh, dbih, dbhh, wr, s->ws, bias, b, warp, lane, tid);
    const int maxlen = *maxlen_p;
    __syncthreads();

    // ---- decoder ----
    for (int d = 0; d < maxlen; d++) {
        const unsigned eh = base + 1 + (unsigned)(seq + d);
        if (tid == 0) {
            wait_ge(&g_flag2[0], eh);
            s->done = __ldcg(&g_done);
        }
        __syncthreads();
        if (s->done) break;

        int p = (seq + d) & 1;
        if (tid < 128) {
            ((float4*)s->xh)[tid] = __ldcg(((const float4*)g_cur_emb) + tid);
            wait_ge(&g_flags[tid * FSTR], eh);
            const float4* hp = (const float4*)(g_h[p] + tid * UNITS);
            float4 v0 = __ldcg(hp), v1 = __ldcg(hp + 1);
            ((float4*)(s->xh + EMB))[tid * 2 + 0] = v0;
            ((float4*)(s->xh + EMB))[tid * 2 + 1] = v1;
        }
        __syncthreads();

        u64t acc[4] = {0ull, 0ull, 0ull, 0ull};
        mac_reg<0, JR>(wr, s->xh, lane, acc);
        mac_sm(s->ws, s->xh, warp, lane, acc);
        float hn = finish_unit(acc, bias, lane, cstate);
        if (lane == 0) __stcg(&g_h[p ^ 1][b * UNITS + warp], hn);
        __syncthreads();
        if (tid == 0) st_rel(&g_flags[b * FSTR], eh + 1);

        if (b == 0) {  // projection + greedy feedback
            if (tid < 128) wait_ge(&g_flags[tid * FSTR], eh + 1);
            __syncthreads();
            if (warp < OUTC) {
                const float* hrow = g_h[p ^ 1];
                float a = 0.0f;
                for (int k = lane; k < HID; k += 32)
                    a += __ldcg(hrow + k) * outW[(size_t)warp * HID + k];
#pragma unroll
                for (int off = 16; off; off >>= 1)
                    a += __shfl_xor_sync(0xffffffffu, a, off);
                if (lane == 0) s->pred[warp] = a + outb[warp];
            }
            __syncthreads();
            if (tid == 0) {
                for (int o = 0; o < OUTC; o++) out[d * OUTC + o] = s->pred[o];
                if (maxlen * OUTC + d < out_size) out[maxlen * OUTC + d] = 1.0f;
                float r = rintf(s->pred[0]);
                r = fminf(fmaxf(r, 0.0f), (float)(VOCAB - 1));
                int nid = (int)r;
                s->nid = nid;
                if (nid == EOS_TOK) g_done = 1;
            }
            __syncthreads();
            int nid = s->nid;
            float sc = (nid != PAD_TOK) ? 1.0f : 0.0f;
            for (int k = tid; k < EMB; k += NTH)
                g_cur_emb[k] = emb[(size_t)nid * EMB + k] * sc;
            __syncthreads();
            if (tid == 0) st_rel(&g_flag2[0], eh + 1);
        }
    }
}

extern "C" void kernel_launch(void* const* d_in, const int* in_sizes, int n_in,
                              void* d_out, int out_size)
{
    const int*   x    = (const int*)  d_in[0];
    const float* emb  = (const float*)d_in[1];
    const float* eWih = (const float*)d_in[2];
    const float* eWhh = (const float*)d_in[3];
    const float* ebih = (const float*)d_in[4];
    const float* ebhh = (const float*)d_in[5];
    const float* dWih = (const float*)d_in[6];
    const float* dWhh = (const float*)d_in[7];
    const float* dbih = (const float*)d_in[8];
    const float* dbhh = (const float*)d_in[9];
    const float* outW = (const float*)d_in[10];
    const float* outb = (const float*)d_in[11];
    const int*   mlp  = (const int*)  d_in[12];
    int seq = in_sizes[0];

    int smem_bytes = (int)sizeof(SM);
    cudaFuncSetAttribute(seq2seq_kernel,
                         cudaFuncAttributeMaxDynamicSharedMemorySize, smem_bytes);

    seq2seq_kernel<<<NBLK, NTH, smem_bytes>>>(
        x, seq, emb, eWih, eWhh, ebih, ebhh,
        dWih, dWhh, dbih, dbhh, outW, outb, mlp,
        (float*)d_out, out_size);
}

// round 9
// speedup vs baseline: 1.6372x; 1.0298x over previous
#include <cuda_runtime.h>
#include <math.h>

// ---------------- problem constants ----------------
#define PAD_TOK 0
#define SOS_TOK 1
#define EOS_TOK 2
#define VOCAB   50000
#define EMB     512
#define HID     1024
#define OUTC    5

// ---------------- kernel geometry ----------------
#define NBLK   128          // persistent CTAs, all co-resident
#define NTH    256
#define UNITS  8            // hidden units per CTA (warp u owns unit u)
#define KTOT   (EMB + HID)  // 1536
#define NJX    8            // x chunks (k = j*64+lane*2, k < 512)   -> weights in SMEM
#define NJH    16           // h chunks (k = EMB + j*64+lane*2)      -> weights in REGS
#define XWS_ROW 512         // floats per xws row
#define TOKCAP 2048
#define FSTR   32

// ---------------- global state (r4-proven protocol) ----------------
__device__ unsigned g_flags[NBLK * FSTR];   // per-CTA h epoch flags
__device__ unsigned g_flag2[FSTR];          // block0 -> all (emb/done epoch)
__device__ __align__(16) float g_h[2][HID];
__device__ __align__(16) float g_cur_emb[EMB];
__device__ int g_done;

// ---------------- sync primitives ----------------
__device__ __forceinline__ unsigned ld_acq(const unsigned* p) {
    unsigned v;
    asm volatile("ld.acquire.gpu.global.u32 %0, [%1];" : "=r"(v) : "l"(p) : "memory");
    return v;
}
__device__ __forceinline__ void st_rel(unsigned* p, unsigned v) {
    asm volatile("st.release.gpu.global.u32 [%0], %1;" :: "l"(p), "r"(v) : "memory");
}
__device__ __forceinline__ void wait_ge(const unsigned* p, unsigned tgt) {
    while ((int)(ld_acq(p) - tgt) < 0) { }
}

// ---------------- packed dual-FMA (Blackwell f32x2) ----------------
typedef unsigned long long u64t;
__device__ __forceinline__ void fma2(u64t& d, u64t a, u64t b) {
    asm("fma.rn.f32x2 %0, %1, %2, %0;" : "+l"(d) : "l"(a), "l"(b));
}
__device__ __forceinline__ float f2lo(u64t v) { return __uint_as_float((unsigned)v); }
__device__ __forceinline__ float f2hi(u64t v) { return __uint_as_float((unsigned)(v >> 32)); }

// ---------------- fast activations (proven in r3/r4) ----------------
__device__ __forceinline__ float fsig(float x)  { return __fdividef(1.0f, 1.0f + __expf(-x)); }
__device__ __forceinline__ float ftanh(float x) { return 1.0f - __fdividef(2.0f, __expf(2.0f * x) + 1.0f); }

// ---------------- smem plan ----------------
struct SM {
    float xh[KTOT];
    float xws[32 * XWS_ROW];   // x-part weights, rows r = q*8+u (64 KB)
    int   x_tok[TOKCAP];
    float pred[OUTC];
    int   nid;
    int   done;
    unsigned sbase;
};

// ---------------- weight load: h-part -> regs, x-part -> smem ----------------
__device__ __forceinline__ void load_w(
    const float* __restrict__ Wih, const float* __restrict__ Whh,
    const float* __restrict__ bih, const float* __restrict__ bhh,
    u64t (&wr)[4][NJH], float* xws, float (&bias)[4],
    int b, int u, int lane, int tid)
{
#pragma unroll
    for (int q = 0; q < 4; q++) {
        size_t G = (size_t)q * HID + (size_t)b * UNITS + u;
        const float* rh = Whh + G * HID;
#pragma unroll
        for (int j = 0; j < NJH; j++)
            wr[q][j] = *(const u64t*)(rh + j * 64 + lane * 2);
    }
    // x-part weights to smem: 32 rows x 512 floats = 4096 float4
    for (int i = tid; i < 32 * (XWS_ROW / 4); i += NTH) {
        int r = i >> 7, c = i & 127;                 // 128 float4 per row
        int q = r >> 3, uu = r & 7;
        size_t G = (size_t)q * HID + (size_t)b * UNITS + uu;
        ((float4*)(xws + (size_t)r * XWS_ROW))[c] = ((const float4*)(Wih + G * EMB))[c];
    }
    if (lane == 0) {
#pragma unroll
        for (int q = 0; q < 4; q++) {
            size_t G = (size_t)q * HID + (size_t)b * UNITS + u;
            bias[q] = bih[G] + bhh[G];
        }
    }
}

// x-part MAC from smem weights (runs inside the flag-wait overlap window)
__device__ __forceinline__ void mac_x(const float* xws, const float* xh,
                                      int u, int lane, u64t (&acc)[4])
{
#pragma unroll
    for (int j = 0; j < NJX; j++) {
        u64t v = *(const u64t*)(xh + j * 64 + lane * 2);
#pragma unroll
        for (int q = 0; q < 4; q++) {
            u64t wv = *(const u64t*)(xws + (size_t)(q * 8 + u) * XWS_ROW
                                         + j * 64 + lane * 2);
            fma2(acc[q], wv, v);
        }
    }
}

// h-part MAC: all weights in registers (critical path)
__device__ __forceinline__ void mac_h(const u64t (&wr)[4][NJH], const float* xh,
                                      int lane, u64t (&acc)[4])
{
#pragma unroll
    for (int j = 0; j < NJH; j++) {
        u64t v = *(const u64t*)(xh + EMB + j * 64 + lane * 2);
        fma2(acc[0], wr[0][j], v);
        fma2(acc[1], wr[1][j], v);
        fma2(acc[2], wr[2][j], v);
        fma2(acc[3], wr[3][j], v);
    }
}

__device__ __forceinline__ float finish_unit(u64t (&acc)[4], const float (&bias)[4],
                                             int lane, float& cstate)
{
    float a0 = f2lo(acc[0]) + f2hi(acc[0]);
    float a1 = f2lo(acc[1]) + f2hi(acc[1]);
    float a2 = f2lo(acc[2]) + f2hi(acc[2]);
    float a3 = f2lo(acc[3]) + f2hi(acc[3]);
#pragma unroll
    for (int off = 16; off; off >>= 1) {
        a0 += __shfl_xor_sync(0xffffffffu, a0, off);
        a1 += __shfl_xor_sync(0xffffffffu, a1, off);
        a2 += __shfl_xor_sync(0xffffffffu, a2, off);
        a3 += __shfl_xor_sync(0xffffffffu, a3, off);
    }
    float hn = 0.0f;
    if (lane == 0) {
        float gi = a0 + bias[0], gf = a1 + bias[1];
        float gg = a2 + bias[2], go = a3 + bias[3];
        float cn = fsig(gf) * cstate + fsig(gi) * ftanh(gg);
        hn = fsig(go) * ftanh(cn);
        cstate = cn;
    }
    return hn;
}

extern __shared__ __align__(16) unsigned char smem_raw[];

__global__ void __launch_bounds__(NTH, 1)
seq2seq_kernel(const int* __restrict__ x_ids, int seq,
               const float* __restrict__ emb,
               const float* __restrict__ eWih, const float* __restrict__ eWhh,
               const float* __restrict__ ebih, const float* __restrict__ ebhh,
               const float* __restrict__ dWih, const float* __restrict__ dWhh,
               const float* __restrict__ dbih, const float* __restrict__ dbhh,
               const float* __restrict__ outW, const float* __restrict__ outb,
               const int* __restrict__ maxlen_p,
               float* __restrict__ out, int out_size)
{
    SM* s = (SM*)smem_raw;
    const int tid = threadIdx.x;
    const int b = blockIdx.x;
    const int warp = tid >> 5, lane = tid & 31;   // warp == unit u

    // flag base (own flag: exact, uniform across CTAs at replay boundaries)
    if (tid == 0) s->sbase = __ldcg(&g_flags[b * FSTR]);

    u64t wr[4][NJH];
    float bias[4] = {0.f, 0.f, 0.f, 0.f};
    load_w(eWih, eWhh, ebih, ebhh, wr, s->xws, bias, b, warp, lane, tid);
    float cstate = 0.0f;
    for (int k = tid; k < seq && k < TOKCAP; k += NTH) s->x_tok[k] = x_ids[k];
    __syncthreads();
    const unsigned base = s->sbase;

    if (tid == 0) {                                 // publish h_0 = 0
        float4 z = make_float4(0.f, 0.f, 0.f, 0.f);
        float4* dst = (float4*)(g_h[0] + b * UNITS);
        __stcg(dst, z); __stcg(dst + 1, z);
        st_rel(&g_flags[b * FSTR], base + 1);
    }
    if (b == 0) {                                   // publish emb_0 / done_0
        for (int k = tid; k < out_size; k += NTH) out[k] = 0.0f;
        if (tid < EMB / 4)
            __stcg(((float4*)g_cur_emb) + tid,
                   ((const float4*)(emb + (size_t)SOS_TOK * EMB))[tid]);
        if (tid == 0) g_done = 0;
        __syncthreads();
        if (tid == 0) st_rel(&g_flag2[0], base + 1 + (unsigned)seq);
    }

    // x-part of xh for t=0
    float4 epf = make_float4(0.f, 0.f, 0.f, 0.f);
    if (tid < 128 && seq > 0) {
        int tok0 = s->x_tok[0];
        epf = ((const float4*)(emb + (size_t)tok0 * EMB))[tid];
        ((float4*)s->xh)[tid] = epf;
    }
    __syncthreads();

    // ---- encoder (r4 protocol; x-MAC from smem overlaps the wait) ----
    for (int t = 0; t < seq; t++) {
        u64t acc[4] = {0ull, 0ull, 0ull, 0ull};
        mac_x(s->xws, s->xh, warp, lane, acc);           // overlap window work

        if (tid < 128) {
            if (t + 1 < seq) {                            // prefetch next emb row
                int tk = (t + 1 < TOKCAP) ? s->x_tok[t + 1] : __ldg(&x_ids[t + 1]);
                epf = ((const float4*)(emb + (size_t)tk * EMB))[tid];
            }
            wait_ge(&g_flags[tid * FSTR], base + 1 + (unsigned)t);
            const float4* hp = (const float4*)(g_h[t & 1] + tid * UNITS);
            float4 v0 = __ldcg(hp), v1 = __ldcg(hp + 1);
            ((float4*)(s->xh + EMB))[tid * 2 + 0] = v0;
            ((float4*)(s->xh + EMB))[tid * 2 + 1] = v1;
        }
        __syncthreads();

        mac_h(wr, s->xh, lane, acc);                      // critical path: regs only
        float hn = finish_unit(acc, bias, lane, cstate);

        if (tid < 128) ((float4*)s->xh)[tid] = epf;       // stage x_{t+1}
        if (lane == 0) __stcg(&g_h[(t + 1) & 1][b * UNITS + warp], hn);
        __syncthreads();
        if (tid == 0) st_rel(&g_flags[b * FSTR], base + 2 + (unsigned)t);
    }

    // ---- decoder weights ----
    load_w(dWih, dWhh, dbih, dbhh, wr, s->xws, bias, b, warp, lane, tid);
    const int maxlen = *maxlen_p;
    __syncthreads();

    // ---- decoder (r4 protocol verbatim) ----
    for (int d = 0; d < maxlen; d++) {
        const unsigned eh = base + 1 + (unsigned)(seq + d);
        if (tid == 0) {
            wait_ge(&g_flag2[0], eh);
            s->done = __ldcg(&g_done);
        }
        __syncthreads();
        if (s->done) break;

        int p = (seq + d) & 1;
        if (tid < 128) {
            ((float4*)s->xh)[tid] = __ldcg(((const float4*)g_cur_emb) + tid);
            wait_ge(&g_flags[tid * FSTR], eh);
            const float4* hp = (const float4*)(g_h[p] + tid * UNITS);
            float4 v0 = __ldcg(hp), v1 = __ldcg(hp + 1);
            ((float4*)(s->xh + EMB))[tid * 2 + 0] = v0;
            ((float4*)(s->xh + EMB))[tid * 2 + 1] = v1;
        }
        __syncthreads();

        u64t acc[4] = {0ull, 0ull, 0ull, 0ull};
        mac_x(s->xws, s->xh, warp, lane, acc);
        mac_h(wr, s->xh, lane, acc);
        float hn = finish_unit(acc, bias, lane, cstate);
        if (lane == 0) __stcg(&g_h[p ^ 1][b * UNITS + warp], hn);
        __syncthreads();
        if (tid == 0) st_rel(&g_flags[b * FSTR], eh + 1);

        // block 0: projection (reads GLOBAL g_h), greedy feedback
        if (b == 0) {
            if (tid < 128) wait_ge(&g_flags[tid * FSTR], eh + 1);
            __syncthreads();
            if (warp < OUTC) {
                const float* hrow = g_h[p ^ 1];
                float a = 0.0f;
                for (int k = lane; k < HID; k += 32)
                    a += __ldcg(hrow + k) * outW[(size_t)warp * HID + k];
#pragma unroll
                for (int off = 16; off; off >>= 1)
                    a += __shfl_xor_sync(0xffffffffu, a, off);
                if (lane == 0) s->pred[warp] = a + outb[warp];
            }
            __syncthreads();
            if (tid == 0) {
                for (int o = 0; o < OUTC; o++) out[d * OUTC + o] = s->pred[o];
                if (maxlen * OUTC + d < out_size) out[maxlen * OUTC + d] = 1.0f;
                float r = rintf(s->pred[0]);             // half-to-even like jnp.round
                r = fminf(fmaxf(r, 0.0f), (float)(VOCAB - 1));
                int nid = (int)r;
                s->nid = nid;
                if (nid == EOS_TOK) g_done = 1;
            }
            __syncthreads();
            int nid = s->nid;
            float sc = (nid != PAD_TOK) ? 1.0f : 0.0f;
            for (int k = tid; k < EMB; k += NTH)
                __stcg(&g_cur_emb[k], emb[(size_t)nid * EMB + k] * sc);
            __syncthreads();
            if (tid == 0) st_rel(&g_flag2[0], eh + 1);
        }
        __syncthreads();
    }
}

extern "C" void kernel_launch(void* const* d_in, const int* in_sizes, int n_in,
                              void* d_out, int out_size)
{
    const int*   x    = (const int*)  d_in[0];
    const float* emb  = (const float*)d_in[1];
    const float* eWih = (const float*)d_in[2];
    const float* eWhh = (const float*)d_in[3];
    const float* ebih = (const float*)d_in[4];
    const float* ebhh = (const float*)d_in[5];
    const float* dWih = (const float*)d_in[6];
    const float* dWhh = (const float*)d_in[7];
    const float* dbih = (const float*)d_in[8];
    const float* dbhh = (const float*)d_in[9];
    const float* outW = (const float*)d_in[10];
    const float* outb = (const float*)d_in[11];
    const int*   mlp  = (const int*)  d_in[12];
    int seq = in_sizes[0];

    int smem_bytes = (int)sizeof(SM);
    cudaFuncSetAttribute(seq2seq_kernel,
                         cudaFuncAttributeMaxDynamicSharedMemorySize, smem_bytes);

    seq2seq_kernel<<<NBLK, NTH, smem_bytes>>>(
        x, seq, emb, eWih, eWhh, ebih, ebhh,
        dWih, dWhh, dbih, dbhh, outW, outb, mlp,
        (float*)d_out, out_size);
}